// round 13
// baseline (speedup 1.0000x reference)
#include <cuda_runtime.h>
#include <stdint.h>

// KVEmbedding: out[b,l,:] = table[indices[b,l], :]
// indices: int32 [819200], table: float32 [1000000,64], out: float32 [819200,64]
// FINAL (best measured: 61.9us bench / 57.2-58.3us kernel): latency-optimal
// random gather at the mixed-stream DRAM roofline (~5.8 TB/s combined, ~73%
// of spec). 16 threads/row, float4 transfers, 4 rows per slot (one int4
// index load -> 4 independent table LDG.128 in flight), evict-first output
// stores.
//
// Convergence established by experiment across R3-R12:
//   - MLP 1->4: -23% (the win). MLP 4->8: neutral (R4).
//   - 256-bit v8 loads: regress, 2x L1 wavefronts per load (R6).
//   - L2 createpolicy evict_last pinning: dead at 420K & 470K doses (R7/R8);
//     natural LRU already captures all cross-replay reuse (~42% read hits).
//   - ALU trims: invisible at issue% = 8 (R10).
//   - Four identical-SASS benches: 61.9-64.0us = noise band (R9-R12).
// Irreducible traffic: 210MB compulsory writes + ~125MB post-L2 random
// 256B reads (unique working set 143MB > 126MB L2). Gap to spec BW is
// DRAM row-turnaround on mixed random-read/streaming-write traffic.

static constexpr int LANES_PER_ROW = 16;   // 64 floats = 16 x float4
static constexpr int THREADS = 256;
static constexpr int ROWS_PER_SLOT = 4;    // rows handled per 16-thread slot
static constexpr int SLOTS_PER_BLOCK = THREADS / LANES_PER_ROW;        // 16
static constexpr int ROWS_PER_BLOCK = SLOTS_PER_BLOCK * ROWS_PER_SLOT; // 64

__global__ __launch_bounds__(THREADS)
void kv_gather4_kernel(const int* __restrict__ indices,
                       const float4* __restrict__ table4,
                       float4* __restrict__ out4,
                       int n_rows) {
    int slot = blockIdx.x * SLOTS_PER_BLOCK + (threadIdx.x >> 4);
    int lane = threadIdx.x & 15;
    int row0 = slot * ROWS_PER_SLOT;
    if (row0 >= n_rows) return;

    if (row0 + ROWS_PER_SLOT <= n_rows) {
        // Fast path: one 128-bit index load, 4 independent table loads.
        int4 iv = *reinterpret_cast<const int4*>(indices + row0);
        size_t o0 = (size_t)(unsigned)iv.x * LANES_PER_ROW + lane;
        size_t o1 = (size_t)(unsigned)iv.y * LANES_PER_ROW + lane;
        size_t o2 = (size_t)(unsigned)iv.z * LANES_PER_ROW + lane;
        size_t o3 = (size_t)(unsigned)iv.w * LANES_PER_ROW + lane;

        float4 v0 = __ldg(&table4[o0]);
        float4 v1 = __ldg(&table4[o1]);
        float4 v2 = __ldg(&table4[o2]);
        float4 v3 = __ldg(&table4[o3]);

        size_t ob = (size_t)row0 * LANES_PER_ROW + lane;
        __stcs(&out4[ob + 0 * LANES_PER_ROW], v0);
        __stcs(&out4[ob + 1 * LANES_PER_ROW], v1);
        __stcs(&out4[ob + 2 * LANES_PER_ROW], v2);
        __stcs(&out4[ob + 3 * LANES_PER_ROW], v3);
    } else {
        // Tail (unused for 819200 rows, kept for generality).
        for (int r = row0; r < n_rows; r++) {
            unsigned idx = (unsigned)__ldg(&indices[r]);
            float4 v = __ldg(&table4[(size_t)idx * LANES_PER_ROW + lane]);
            __stcs(&out4[(size_t)r * LANES_PER_ROW + lane], v);
        }
    }
}

extern "C" void kernel_launch(void* const* d_in, const int* in_sizes, int n_in,
                              void* d_out, int out_size) {
    const int*   indices = (const int*)d_in[0];
    const float* table   = (const float*)d_in[1];
    // d_in[2] = dummy, contributes exactly 0 — ignored.

    int n_rows = in_sizes[0];

    dim3 grid((n_rows + ROWS_PER_BLOCK - 1) / ROWS_PER_BLOCK);
    kv_gather4_kernel<<<grid, THREADS>>>(indices,
                                         (const float4*)table,
                                         (float4*)d_out,
                                         n_rows);
}